// round 9
// baseline (speedup 1.0000x reference)
#include <cuda_runtime.h>
#include <cuda_fp16.h>
#include <cstdint>

#define B_ 4
#define N_ 4096
#define C_ 1024
#define H_ 16
#define D_ 64
#define M_TOT (B_*N_)    // 16384
#define QKV_N (3*C_)     // 3072

// ---------------- scratch (device globals; no runtime alloc) ----------------
__device__ float  g_qkv[(size_t)M_TOT * QKV_N];        // 201 MB
__device__ float  g_ctx[(size_t)B_ * H_ * D_ * D_];    // 1 MB
__device__ float  g_ctxp[8][(size_t)B_ * H_ * D_ * D_];// 8 MB partials
__device__ __half g_abuf[(size_t)M_TOT * C_];          // 32 MB (x-half, then attn-half)
__device__ __half g_wqkvT[(size_t)QKV_N * C_];         // 6 MB
__device__ __half g_wprojT[(size_t)C_ * C_];           // 2 MB

__device__ __forceinline__ uint32_t smem_u32(const void* p) {
    uint32_t a;
    asm("{ .reg .u64 t; cvta.to.shared.u64 t, %1; cvt.u32.u64 %0, t; }" : "=r"(a) : "l"(p));
    return a;
}

#define CP_ASYNC16(saddr, gptr) \
    asm volatile("cp.async.cg.shared.global [%0], [%1], 16;" :: "r"(saddr), "l"(gptr))
#define CP_COMMIT() asm volatile("cp.async.commit_group;" ::: "memory")
#define CP_WAIT2()  asm volatile("cp.async.wait_group 2;" ::: "memory")

#define LDMATRIX_X4(r0, r1, r2, r3, addr) \
    asm volatile("ldmatrix.sync.aligned.m8n8.x4.shared.b16 {%0, %1, %2, %3}, [%4];" \
        : "=r"(r0), "=r"(r1), "=r"(r2), "=r"(r3) : "r"(addr))

__device__ __forceinline__ void mma_16x8x16(
    float* c, uint32_t a0, uint32_t a1, uint32_t a2, uint32_t a3,
    uint32_t b0, uint32_t b1)
{
    asm volatile(
        "mma.sync.aligned.m16n8k16.row.col.f32.f16.f16.f32 "
        "{%0, %1, %2, %3}, {%4, %5, %6, %7}, {%8, %9}, {%0, %1, %2, %3};"
        : "+f"(c[0]), "+f"(c[1]), "+f"(c[2]), "+f"(c[3])
        : "r"(a0), "r"(a1), "r"(a2), "r"(a3), "r"(b0), "r"(b1));
}

// ---------------------------------------------------------------------------
// fp16 warp-MMA GEMM: C[M,N] = A[M,K] @ Bt[N,K]^T + bias   (fp32 accum)
// BM=128, BN=128, BK=32 halves, 4-stage cp.async pipeline, ldmatrix loads.
// 4 warps (2m x 2n), warp tile 64x64, m16n8k16.
// A, Bt are __half (pre-rounded by producers). Bias/output fp32.
// ---------------------------------------------------------------------------
#define LDTH 40                       // halves per row (32 + 8 pad) = 80 bytes
#define ROWB 80                       // row bytes
#define STAGE_OP_BYTES (128 * ROWB)   // per operand per stage = 10240
#define STAGE_BYTES  (2 * STAGE_OP_BYTES)   // A+B = 20480
#define GEMM_SMEM    (4 * STAGE_BYTES)      // 81920

__global__ __launch_bounds__(128, 2) void gemm_mma_fp16(
    const __half* __restrict__ A, const __half* __restrict__ Bt,
    const float* __restrict__ bias, float* __restrict__ Cm,
    int M, int N, int K)
{
    extern __shared__ char smem[];
    const uint32_t smem_base = smem_u32(smem);

    const int tid = threadIdx.x;
    const int lane = tid & 31;
    const int wid = tid >> 5;
    const int wm = (wid >> 1) * 64;
    const int wn = (wid & 1) * 64;
    const int m0 = blockIdx.y * 128, n0 = blockIdx.x * 128;

    const __half* Ag = A + (size_t)m0 * K;
    const __half* Bg = Bt + (size_t)n0 * K;

    // cp.async: row base = tid>>2 (0..31), chunk = (tid&3)*16 B (8 halves)
    const int r0 = tid >> 2;
    const int kb = (tid & 3) * 16;   // byte offset in row
    const int kf = (tid & 3) * 8;    // half offset

    const int g = lane >> 2;
    const int t4 = lane & 3;

    // ldmatrix byte offsets (stage-relative)
    // A (mt): row = wm+mt*16+(lane&15), byte col = (lane>>4)*16
    uint32_t a_off[4];
    #pragma unroll
    for (int mt = 0; mt < 4; mt++)
        a_off[mt] = (uint32_t)((wm + mt * 16 + (lane & 15)) * ROWB + ((lane >> 4) << 4));
    // B (p covers nt pair): row = wn+p*16+((lane>>4)<<3)+(lane&7), byte col = ((lane>>3)&1)*16
    uint32_t b_off[4];
    #pragma unroll
    for (int p = 0; p < 4; p++)
        b_off[p] = (uint32_t)((wn + p * 16 + ((lane >> 4) << 3) + (lane & 7)) * ROWB
                              + (((lane >> 3) & 1) << 4) + STAGE_OP_BYTES);

    float acc[4][8][4];
    #pragma unroll
    for (int i = 0; i < 4; i++)
        #pragma unroll
        for (int j = 0; j < 8; j++)
            #pragma unroll
            for (int q = 0; q < 4; q++) acc[i][j][q] = 0.f;

    const int iters = K >> 5;   // BK=32 halves

    // prologue: stages 0..2   (8 cp.async per thread per stage: 4 rows x A,B)
    #pragma unroll
    for (int s = 0; s < 3; s++) {
        const uint32_t sa = smem_base + s * STAGE_BYTES;
        const uint32_t sb = sa + STAGE_OP_BYTES;
        const __half* Asrc = Ag + s * 32;
        const __half* Bsrc = Bg + s * 32;
        #pragma unroll
        for (int rr = 0; rr < 4; rr++) {
            const int row = r0 + rr * 32;
            CP_ASYNC16(sa + row * ROWB + kb, Asrc + (size_t)row * K + kf);
            CP_ASYNC16(sb + row * ROWB + kb, Bsrc + (size_t)row * K + kf);
        }
        CP_COMMIT();
    }

    for (int it = 0; it < iters; it++) {
        CP_WAIT2();
        __syncthreads();

        if (it + 3 < iters) {
            const int s = (it + 3) & 3;
            const uint32_t sa = smem_base + s * STAGE_BYTES;
            const uint32_t sb = sa + STAGE_OP_BYTES;
            const __half* Asrc = Ag + (it + 3) * 32;
            const __half* Bsrc = Bg + (it + 3) * 32;
            #pragma unroll
            for (int rr = 0; rr < 4; rr++) {
                const int row = r0 + rr * 32;
                CP_ASYNC16(sa + row * ROWB + kb, Asrc + (size_t)row * K + kf);
                CP_ASYNC16(sb + row * ROWB + kb, Bsrc + (size_t)row * K + kf);
            }
        }
        CP_COMMIT();

        const uint32_t stage = smem_base + (it & 3) * STAGE_BYTES;

        #pragma unroll
        for (int s = 0; s < 2; s++) {           // two K=16 steps per iter
            const uint32_t ksb = (uint32_t)(s * 32);   // 16 halves = 32 B
            uint32_t afr[4][4];
            #pragma unroll
            for (int mt = 0; mt < 4; mt++)
                LDMATRIX_X4(afr[mt][0], afr[mt][1], afr[mt][2], afr[mt][3],
                            stage + a_off[mt] + ksb);
            uint32_t bfr[4][4];
            #pragma unroll
            for (int p = 0; p < 4; p++)
                LDMATRIX_X4(bfr[p][0], bfr[p][1], bfr[p][2], bfr[p][3],
                            stage + b_off[p] + ksb);
            #pragma unroll
            for (int nt = 0; nt < 8; nt++) {
                uint32_t b0 = bfr[nt >> 1][(nt & 1) * 2];
                uint32_t b1 = bfr[nt >> 1][(nt & 1) * 2 + 1];
                #pragma unroll
                for (int mt = 0; mt < 4; mt++)
                    mma_16x8x16(acc[mt][nt], afr[mt][0], afr[mt][1], afr[mt][2], afr[mt][3], b0, b1);
            }
        }
    }

    #pragma unroll
    for (int mt = 0; mt < 4; mt++) {
        #pragma unroll
        for (int nt = 0; nt < 8; nt++) {
            int row = m0 + wm + mt * 16 + g;
            int col = n0 + wn + nt * 8 + t4 * 2;
            float bx = bias[col], by = bias[col + 1];
            float2 o0 = {acc[mt][nt][0] + bx, acc[mt][nt][1] + by};
            float2 o1 = {acc[mt][nt][2] + bx, acc[mt][nt][3] + by};
            *(float2*)&Cm[(size_t)row * N + col] = o0;
            *(float2*)&Cm[(size_t)(row + 8) * N + col] = o1;
        }
    }
}

// ---------------------------------------------------------------------------
// W [K,N] fp32 -> Wt [N,K] fp16 transpose
// ---------------------------------------------------------------------------
__global__ void transpose_kernel(const float* __restrict__ W, __half* __restrict__ Wt,
                                 int K, int N)
{
    __shared__ float t[32][33];
    int n0 = blockIdx.x * 32, k0 = blockIdx.y * 32;
    for (int i = threadIdx.y; i < 32; i += 8)
        t[i][threadIdx.x] = W[(size_t)(k0 + i) * N + n0 + threadIdx.x];
    __syncthreads();
    for (int i = threadIdx.y; i < 32; i += 8)
        Wt[(size_t)(n0 + i) * K + k0 + threadIdx.x] = __float2half_rn(t[threadIdx.x][i]);
}

// round x -> fp16
__global__ __launch_bounds__(256) void round_x_kernel(
    const float* __restrict__ x, __half* __restrict__ xh)
{
    size_t i = ((size_t)blockIdx.x * 256 + threadIdx.x) * 4;
    float4 v = *(const float4*)(x + i);
    __half2 h0 = __floats2half2_rn(v.x, v.y);
    __half2 h1 = __floats2half2_rn(v.z, v.w);
    uint2 o = {*(uint32_t*)&h0, *(uint32_t*)&h1};
    *(uint2*)(xh + i) = o;
}

// ---------------------------------------------------------------------------
// q softmax over head_dim (64 contiguous floats). One warp per (b,n,h).
// ---------------------------------------------------------------------------
__global__ __launch_bounds__(256) void qsoftmax_kernel(float* __restrict__ qkv)
{
    int warp = (blockIdx.x * blockDim.x + threadIdx.x) >> 5;
    int lane = threadIdx.x & 31;
    if (warp >= M_TOT * H_) return;
    int bn = warp >> 4;
    int h  = warp & 15;
    float* p = qkv + (size_t)bn * QKV_N + h * D_;
    float v0 = p[lane];
    float v1 = p[lane + 32];
    float m = fmaxf(v0, v1);
    #pragma unroll
    for (int o = 16; o; o >>= 1) m = fmaxf(m, __shfl_xor_sync(0xffffffffu, m, o));
    float e0 = __expf(v0 - m);
    float e1 = __expf(v1 - m);
    float s = e0 + e1;
    #pragma unroll
    for (int o = 16; o; o >>= 1) s += __shfl_xor_sync(0xffffffffu, s, o);
    float inv = 1.f / s;
    p[lane]      = e0 * inv;
    p[lane + 32] = e1 * inv;
}

// ---------------------------------------------------------------------------
// k softmax over sequence N (column softmax), 2-pass.
// ---------------------------------------------------------------------------
__global__ void ksoftmax_kernel(float* __restrict__ qkv)
{
    int b  = blockIdx.y;
    int cg = blockIdx.x;
    int tx = threadIdx.x;
    int ty = threadIdx.y;
    int col = C_ + cg * 32 + tx;
    float* p = qkv + (size_t)b * N_ * QKV_N + col;

    __shared__ float red[8][33];
    __shared__ float cinv[32];

    float s = 0.f;
    for (int n = ty; n < N_; n += 8)
        s += __expf(p[(size_t)n * QKV_N]);
    red[ty][tx] = s;
    __syncthreads();
    if (ty == 0) {
        float ss = red[0][tx];
        #pragma unroll
        for (int i = 1; i < 8; i++) ss += red[i][tx];
        cinv[tx] = 1.f / ss;
    }
    __syncthreads();
    float inv = cinv[tx];

    for (int n = ty; n < N_; n += 8) {
        float v = p[(size_t)n * QKV_N];
        p[(size_t)n * QKV_N] = __expf(v) * inv;
    }
}

// ---------------------------------------------------------------------------
// ctx partial: grid (B*H, 8). Each block: 64x64 over an N-chunk of 512.
// ---------------------------------------------------------------------------
__global__ __launch_bounds__(256) void ctx_partial_kernel(
    const float* __restrict__ qkv, float* __restrict__ ctxp)
{
    int bh = blockIdx.x;
    int chunk = blockIdx.y;
    int b = bh >> 4, h = bh & 15;
    const float* kbase = qkv + (size_t)b * N_ * QKV_N + C_     + h * D_;
    const float* vbase = qkv + (size_t)b * N_ * QKV_N + 2 * C_ + h * D_;

    __shared__ float Ks[32][64];
    __shared__ float Vs[32][64];

    int tid = threadIdx.x;
    int tx = tid & 15, ty = tid >> 4;
    int ln = tid >> 3;
    int ld = (tid & 7) * 8;

    float acc[4][4];
    #pragma unroll
    for (int i = 0; i < 4; i++)
        #pragma unroll
        for (int j = 0; j < 4; j++) acc[i][j] = 0.f;

    int nbeg = chunk * 512, nend = nbeg + 512;
    for (int nt = nbeg; nt < nend; nt += 32) {
        const float* kp = kbase + (size_t)(nt + ln) * QKV_N + ld;
        const float* vp = vbase + (size_t)(nt + ln) * QKV_N + ld;
        float4 k0 = *(const float4*)kp;
        float4 k1 = *(const float4*)(kp + 4);
        float4 v0 = *(const float4*)vp;
        float4 v1 = *(const float4*)(vp + 4);
        __syncthreads();
        *(float4*)&Ks[ln][ld]     = k0;
        *(float4*)&Ks[ln][ld + 4] = k1;
        *(float4*)&Vs[ln][ld]     = v0;
        *(float4*)&Vs[ln][ld + 4] = v1;
        __syncthreads();

        #pragma unroll 8
        for (int n = 0; n < 32; n++) {
            float4 a = *(float4*)&Ks[n][ty * 4];
            float4 v = *(float4*)&Vs[n][tx * 4];
            float av[4] = {a.x, a.y, a.z, a.w};
            float bv[4] = {v.x, v.y, v.z, v.w};
            #pragma unroll
            for (int i = 0; i < 4; i++)
                #pragma unroll
                for (int j = 0; j < 4; j++)
                    acc[i][j] = fmaf(av[i], bv[j], acc[i][j]);
        }
    }

    float* cp = ctxp + ((size_t)chunk * (B_ * H_) + bh) * D_ * D_;
    #pragma unroll
    for (int i = 0; i < 4; i++) {
        float4 o = {acc[i][0], acc[i][1], acc[i][2], acc[i][3]};
        *(float4*)&cp[(ty * 4 + i) * D_ + tx * 4] = o;
    }
}

__global__ __launch_bounds__(256) void ctx_reduce_kernel(
    const float* __restrict__ ctxp, float* __restrict__ ctx)
{
    int idx = blockIdx.x * 256 + threadIdx.x;
    const int total = B_ * H_ * D_ * D_;
    if (idx >= total) return;
    float s = 0.f;
    #pragma unroll
    for (int c = 0; c < 8; c++) s += ctxp[(size_t)c * total + idx];
    ctx[idx] = s;
}

// ---------------------------------------------------------------------------
// attn[b,n,h*64+e] = sum_d q[b,n,h,d] * ctx[b,h,d,e].  Writes fp16.
// ---------------------------------------------------------------------------
__global__ __launch_bounds__(256) void out_kernel(
    const float* __restrict__ qkv, const float* __restrict__ ctx,
    __half* __restrict__ attn)
{
    int b = blockIdx.z, h = blockIdx.y, n0 = blockIdx.x * 128;

    __shared__ float Cs[64][64];
    __shared__ float Qs[128][64];

    int tid = threadIdx.x;

    const float* cp = ctx + (size_t)(b * H_ + h) * D_ * D_;
    for (int i = tid * 4; i < 4096; i += 1024)
        *(float4*)&Cs[0][i] = *(const float4*)&cp[i];

    const float* qbase = qkv + (size_t)(b * N_ + n0) * QKV_N + h * D_;
    int ln = tid >> 1;
    int ld = (tid & 1) * 32;
    #pragma unroll
    for (int j = 0; j < 32; j += 4)
        *(float4*)&Qs[ln][ld + j] = *(const float4*)&qbase[(size_t)ln * QKV_N + ld + j];
    __syncthreads();

    int tx = tid & 15, ty = tid >> 4;
    float acc[8][4];
    #pragma unroll
    for (int r = 0; r < 8; r++)
        #pragma unroll
        for (int j = 0; j < 4; j++) acc[r][j] = 0.f;

    #pragma unroll 4
    for (int d = 0; d < 64; d++) {
        float4 c4 = *(float4*)&Cs[d][tx * 4];
        #pragma unroll
        for (int r = 0; r < 8; r++) {
            float qv = Qs[ty + 16 * r][d];
            acc[r][0] = fmaf(qv, c4.x, acc[r][0]);
            acc[r][1] = fmaf(qv, c4.y, acc[r][1]);
            acc[r][2] = fmaf(qv, c4.z, acc[r][2]);
            acc[r][3] = fmaf(qv, c4.w, acc[r][3]);
        }
    }

    #pragma unroll
    for (int r = 0; r < 8; r++) {
        int n = n0 + ty + 16 * r;
        __half2 h0 = __floats2half2_rn(acc[r][0], acc[r][1]);
        __half2 h1 = __floats2half2_rn(acc[r][2], acc[r][3]);
        uint2 o = {*(uint32_t*)&h0, *(uint32_t*)&h1};
        *(uint2*)&attn[(size_t)(b * N_ + n) * C_ + h * D_ + tx * 4] = o;
    }
}

// ---------------------------------------------------------------------------
extern "C" void kernel_launch(void* const* d_in, const int* in_sizes, int n_in,
                              void* d_out, int out_size)
{
    (void)in_sizes; (void)n_in; (void)out_size;
    const float* x     = (const float*)d_in[0];
    const float* Wqkv  = (const float*)d_in[1];
    const float* bqkv  = (const float*)d_in[2];
    const float* Wproj = (const float*)d_in[3];
    const float* bproj = (const float*)d_in[4];
    float* out = (float*)d_out;

    float *qkv, *ctx, *ctxp;
    __half *abuf, *wqkvT, *wprojT;
    cudaGetSymbolAddress((void**)&qkv,    g_qkv);
    cudaGetSymbolAddress((void**)&ctx,    g_ctx);
    cudaGetSymbolAddress((void**)&ctxp,   g_ctxp);
    cudaGetSymbolAddress((void**)&abuf,   g_abuf);
    cudaGetSymbolAddress((void**)&wqkvT,  g_wqkvT);
    cudaGetSymbolAddress((void**)&wprojT, g_wprojT);

    cudaFuncSetAttribute(gemm_mma_fp16,
                         cudaFuncAttributeMaxDynamicSharedMemorySize, GEMM_SMEM);

    // 0) convert x to fp16 (into abuf); transpose weights to [N,K] fp16
    round_x_kernel<<<M_TOT * C_ / 1024, 256>>>(x, abuf);
    transpose_kernel<<<dim3(QKV_N / 32, C_ / 32), dim3(32, 8)>>>(Wqkv, wqkvT, C_, QKV_N);
    transpose_kernel<<<dim3(C_ / 32, C_ / 32), dim3(32, 8)>>>(Wproj, wprojT, C_, C_);

    // 1) qkv = x @ W_qkv + b_qkv   (fp16 MMA, fp32 accum)
    gemm_mma_fp16<<<dim3(QKV_N / 128, M_TOT / 128), 128, GEMM_SMEM>>>(
        abuf, wqkvT, bqkv, qkv, M_TOT, QKV_N, C_);

    // 2) q softmax over head_dim
    qsoftmax_kernel<<<(M_TOT * H_) / 8, 256>>>(qkv);

    // 3) k softmax over sequence
    ksoftmax_kernel<<<dim3(32, B_), dim3(32, 8)>>>(qkv);

    // 4) context = k^T v per head (partials + deterministic reduce)
    ctx_partial_kernel<<<dim3(B_ * H_, 8), 256>>>(qkv, ctxp);
    ctx_reduce_kernel<<<(B_ * H_ * D_ * D_ + 255) / 256, 256>>>(ctxp, ctx);

    // 5) attn = q @ context  (fp16 out, overwrites x-half; GEMM1 done with it)
    out_kernel<<<dim3(N_ / 128, H_, B_), 256>>>(qkv, ctx, abuf);

    // 6) out = attn @ W_proj + b_proj
    gemm_mma_fp16<<<dim3(C_ / 128, M_TOT / 128), 128, GEMM_SMEM>>>(
        abuf, wprojT, bproj, out, M_TOT, C_, C_);
}

// round 10
// speedup vs baseline: 1.8547x; 1.8547x over previous
#include <cuda_runtime.h>
#include <cuda_fp16.h>
#include <cstdint>

#define B_ 4
#define N_ 4096
#define C_ 1024
#define H_ 16
#define D_ 64
#define M_TOT (B_*N_)    // 16384
#define QKV_N (3*C_)     // 3072
#define NCHUNK 16
#define CHUNKN (N_/NCHUNK)   // 256

// ---------------- scratch (device globals; no runtime alloc) ----------------
__device__ float  g_qkv[(size_t)M_TOT * QKV_N];          // 201 MB
__device__ float  g_ctx[(size_t)B_ * H_ * D_ * D_];      // 1 MB
__device__ float  g_ctxp[NCHUNK][(size_t)B_ * H_ * D_ * D_]; // 16 MB partials
__device__ float  g_ctxs[NCHUNK][(size_t)B_ * H_ * D_];  // 256 KB exp-sum partials
__device__ __half g_abuf[(size_t)M_TOT * C_];            // 32 MB (x-half, then attn-half)
__device__ __half g_wqkvT[(size_t)QKV_N * C_];           // 6 MB
__device__ __half g_wprojT[(size_t)C_ * C_];             // 2 MB

__device__ __forceinline__ uint32_t smem_u32(const void* p) {
    uint32_t a;
    asm("{ .reg .u64 t; cvta.to.shared.u64 t, %1; cvt.u32.u64 %0, t; }" : "=r"(a) : "l"(p));
    return a;
}

#define CP_ASYNC16(saddr, gptr) \
    asm volatile("cp.async.cg.shared.global [%0], [%1], 16;" :: "r"(saddr), "l"(gptr))
#define CP_COMMIT() asm volatile("cp.async.commit_group;" ::: "memory")
#define CP_WAIT2()  asm volatile("cp.async.wait_group 2;" ::: "memory")

#define LDMATRIX_X4(r0, r1, r2, r3, addr) \
    asm volatile("ldmatrix.sync.aligned.m8n8.x4.shared.b16 {%0, %1, %2, %3}, [%4];" \
        : "=r"(r0), "=r"(r1), "=r"(r2), "=r"(r3) : "r"(addr))

__device__ __forceinline__ void mma_16x8x16(
    float* c, uint32_t a0, uint32_t a1, uint32_t a2, uint32_t a3,
    uint32_t b0, uint32_t b1)
{
    asm volatile(
        "mma.sync.aligned.m16n8k16.row.col.f32.f16.f16.f32 "
        "{%0, %1, %2, %3}, {%4, %5, %6, %7}, {%8, %9}, {%0, %1, %2, %3};"
        : "+f"(c[0]), "+f"(c[1]), "+f"(c[2]), "+f"(c[3])
        : "r"(a0), "r"(a1), "r"(a2), "r"(a3), "r"(b0), "r"(b1));
}

// ---------------------------------------------------------------------------
// fp16 warp-MMA GEMM: C[M,N] = A[M,K] @ Bt[N,K]^T + bias   (fp32 accum)
// BM=128, BN=128, BK=32 halves, 4-stage cp.async pipeline, ldmatrix loads.
// 4 warps (2m x 2n), warp tile 64x64, m16n8k16.
// ---------------------------------------------------------------------------
#define ROWB 80                       // row bytes (32 halves + 8 pad)
#define STAGE_OP_BYTES (128 * ROWB)   // 10240
#define STAGE_BYTES  (2 * STAGE_OP_BYTES)   // 20480
#define GEMM_SMEM    (4 * STAGE_BYTES)      // 81920

__global__ __launch_bounds__(128, 2) void gemm_mma_fp16(
    const __half* __restrict__ A, const __half* __restrict__ Bt,
    const float* __restrict__ bias, float* __restrict__ Cm,
    int M, int N, int K)
{
    extern __shared__ char smem[];
    const uint32_t smem_base = smem_u32(smem);

    const int tid = threadIdx.x;
    const int lane = tid & 31;
    const int wid = tid >> 5;
    const int wm = (wid >> 1) * 64;
    const int wn = (wid & 1) * 64;
    const int m0 = blockIdx.y * 128, n0 = blockIdx.x * 128;

    const __half* Ag = A + (size_t)m0 * K;
    const __half* Bg = Bt + (size_t)n0 * K;

    const int r0 = tid >> 2;
    const int kb = (tid & 3) * 16;
    const int kf = (tid & 3) * 8;

    const int g = lane >> 2;
    const int t4 = lane & 3;

    uint32_t a_off[4];
    #pragma unroll
    for (int mt = 0; mt < 4; mt++)
        a_off[mt] = (uint32_t)((wm + mt * 16 + (lane & 15)) * ROWB + ((lane >> 4) << 4));
    uint32_t b_off[4];
    #pragma unroll
    for (int p = 0; p < 4; p++)
        b_off[p] = (uint32_t)((wn + p * 16 + ((lane >> 4) << 3) + (lane & 7)) * ROWB
                              + (((lane >> 3) & 1) << 4) + STAGE_OP_BYTES);

    float acc[4][8][4];
    #pragma unroll
    for (int i = 0; i < 4; i++)
        #pragma unroll
        for (int j = 0; j < 8; j++)
            #pragma unroll
            for (int q = 0; q < 4; q++) acc[i][j][q] = 0.f;

    const int iters = K >> 5;

    #pragma unroll
    for (int s = 0; s < 3; s++) {
        const uint32_t sa = smem_base + s * STAGE_BYTES;
        const uint32_t sb = sa + STAGE_OP_BYTES;
        const __half* Asrc = Ag + s * 32;
        const __half* Bsrc = Bg + s * 32;
        #pragma unroll
        for (int rr = 0; rr < 4; rr++) {
            const int row = r0 + rr * 32;
            CP_ASYNC16(sa + row * ROWB + kb, Asrc + (size_t)row * K + kf);
            CP_ASYNC16(sb + row * ROWB + kb, Bsrc + (size_t)row * K + kf);
        }
        CP_COMMIT();
    }

    for (int it = 0; it < iters; it++) {
        CP_WAIT2();
        __syncthreads();

        if (it + 3 < iters) {
            const int s = (it + 3) & 3;
            const uint32_t sa = smem_base + s * STAGE_BYTES;
            const uint32_t sb = sa + STAGE_OP_BYTES;
            const __half* Asrc = Ag + (it + 3) * 32;
            const __half* Bsrc = Bg + (it + 3) * 32;
            #pragma unroll
            for (int rr = 0; rr < 4; rr++) {
                const int row = r0 + rr * 32;
                CP_ASYNC16(sa + row * ROWB + kb, Asrc + (size_t)row * K + kf);
                CP_ASYNC16(sb + row * ROWB + kb, Bsrc + (size_t)row * K + kf);
            }
        }
        CP_COMMIT();

        const uint32_t stage = smem_base + (it & 3) * STAGE_BYTES;

        #pragma unroll
        for (int s = 0; s < 2; s++) {
            const uint32_t ksb = (uint32_t)(s * 32);
            uint32_t afr[4][4];
            #pragma unroll
            for (int mt = 0; mt < 4; mt++)
                LDMATRIX_X4(afr[mt][0], afr[mt][1], afr[mt][2], afr[mt][3],
                            stage + a_off[mt] + ksb);
            uint32_t bfr[4][4];
            #pragma unroll
            for (int p = 0; p < 4; p++)
                LDMATRIX_X4(bfr[p][0], bfr[p][1], bfr[p][2], bfr[p][3],
                            stage + b_off[p] + ksb);
            #pragma unroll
            for (int nt = 0; nt < 8; nt++) {
                uint32_t b0 = bfr[nt >> 1][(nt & 1) * 2];
                uint32_t b1 = bfr[nt >> 1][(nt & 1) * 2 + 1];
                #pragma unroll
                for (int mt = 0; mt < 4; mt++)
                    mma_16x8x16(acc[mt][nt], afr[mt][0], afr[mt][1], afr[mt][2], afr[mt][3], b0, b1);
            }
        }
    }

    #pragma unroll
    for (int mt = 0; mt < 4; mt++) {
        #pragma unroll
        for (int nt = 0; nt < 8; nt++) {
            int row = m0 + wm + mt * 16 + g;
            int col = n0 + wn + nt * 8 + t4 * 2;
            float bx = bias[col], by = bias[col + 1];
            float2 o0 = {acc[mt][nt][0] + bx, acc[mt][nt][1] + by};
            float2 o1 = {acc[mt][nt][2] + bx, acc[mt][nt][3] + by};
            *(float2*)&Cm[(size_t)row * N + col] = o0;
            *(float2*)&Cm[(size_t)(row + 8) * N + col] = o1;
        }
    }
}

// ---------------------------------------------------------------------------
// W [K,N] fp32 -> Wt [N,K] fp16 transpose
// ---------------------------------------------------------------------------
__global__ void transpose_kernel(const float* __restrict__ W, __half* __restrict__ Wt,
                                 int K, int N)
{
    __shared__ float t[32][33];
    int n0 = blockIdx.x * 32, k0 = blockIdx.y * 32;
    for (int i = threadIdx.y; i < 32; i += 8)
        t[i][threadIdx.x] = W[(size_t)(k0 + i) * N + n0 + threadIdx.x];
    __syncthreads();
    for (int i = threadIdx.y; i < 32; i += 8)
        Wt[(size_t)(n0 + i) * K + k0 + threadIdx.x] = __float2half_rn(t[threadIdx.x][i]);
}

// round x -> fp16
__global__ __launch_bounds__(256) void round_x_kernel(
    const float* __restrict__ x, __half* __restrict__ xh)
{
    size_t i = ((size_t)blockIdx.x * 256 + threadIdx.x) * 4;
    float4 v = *(const float4*)(x + i);
    __half2 h0 = __floats2half2_rn(v.x, v.y);
    __half2 h1 = __floats2half2_rn(v.z, v.w);
    uint2 o = {*(uint32_t*)&h0, *(uint32_t*)&h1};
    *(uint2*)(xh + i) = o;
}

// ---------------------------------------------------------------------------
// ctx partial (fused k-softmax): reads RAW k,v. Accumulates exp(k)^T v and
// per-d sums of exp(k). grid (B*H, NCHUNK).
// ---------------------------------------------------------------------------
__global__ __launch_bounds__(256) void ctx_partial_kernel(
    const float* __restrict__ qkv, float* __restrict__ ctxp, float* __restrict__ ctxs)
{
    int bh = blockIdx.x;
    int chunk = blockIdx.y;
    int b = bh >> 4, h = bh & 15;
    const float* kbase = qkv + (size_t)b * N_ * QKV_N + C_     + h * D_;
    const float* vbase = qkv + (size_t)b * N_ * QKV_N + 2 * C_ + h * D_;

    __shared__ float Ks[32][64];
    __shared__ float Vs[32][64];

    int tid = threadIdx.x;
    int tx = tid & 15, ty = tid >> 4;
    int ln = tid >> 3;
    int ld = (tid & 7) * 8;

    float acc[4][4];
    float accs[4];
    #pragma unroll
    for (int i = 0; i < 4; i++) {
        accs[i] = 0.f;
        #pragma unroll
        for (int j = 0; j < 4; j++) acc[i][j] = 0.f;
    }

    int nbeg = chunk * CHUNKN, nend = nbeg + CHUNKN;
    for (int nt = nbeg; nt < nend; nt += 32) {
        const float* kp = kbase + (size_t)(nt + ln) * QKV_N + ld;
        const float* vp = vbase + (size_t)(nt + ln) * QKV_N + ld;
        float4 k0 = *(const float4*)kp;
        float4 k1 = *(const float4*)(kp + 4);
        float4 v0 = *(const float4*)vp;
        float4 v1 = *(const float4*)(vp + 4);
        // exp applied at load (k softmax factored: scale by 1/colsum later)
        k0.x = __expf(k0.x); k0.y = __expf(k0.y); k0.z = __expf(k0.z); k0.w = __expf(k0.w);
        k1.x = __expf(k1.x); k1.y = __expf(k1.y); k1.z = __expf(k1.z); k1.w = __expf(k1.w);
        __syncthreads();
        *(float4*)&Ks[ln][ld]     = k0;
        *(float4*)&Ks[ln][ld + 4] = k1;
        *(float4*)&Vs[ln][ld]     = v0;
        *(float4*)&Vs[ln][ld + 4] = v1;
        __syncthreads();

        #pragma unroll 8
        for (int n = 0; n < 32; n++) {
            float4 a = *(float4*)&Ks[n][ty * 4];
            float4 v = *(float4*)&Vs[n][tx * 4];
            float av[4] = {a.x, a.y, a.z, a.w};
            float bv[4] = {v.x, v.y, v.z, v.w};
            #pragma unroll
            for (int i = 0; i < 4; i++) {
                accs[i] += av[i];
                #pragma unroll
                for (int j = 0; j < 4; j++)
                    acc[i][j] = fmaf(av[i], bv[j], acc[i][j]);
            }
        }
    }

    float* cp = ctxp + ((size_t)chunk * (B_ * H_) + bh) * D_ * D_;
    #pragma unroll
    for (int i = 0; i < 4; i++) {
        float4 o = {acc[i][0], acc[i][1], acc[i][2], acc[i][3]};
        *(float4*)&cp[(ty * 4 + i) * D_ + tx * 4] = o;
    }
    if (tx == 0) {
        float* sp = ctxs + (size_t)chunk * (B_ * H_ * D_) + bh * D_;
        #pragma unroll
        for (int i = 0; i < 4; i++)
            sp[ty * 4 + i] = accs[i];   // NOTE: accs[i] duplicated across tx; tx==0 writes
    }
}

// reduce partials + apply 1/colsum scaling
__global__ __launch_bounds__(256) void ctx_reduce_kernel(
    const float* __restrict__ ctxp, const float* __restrict__ ctxs,
    float* __restrict__ ctx)
{
    int idx = blockIdx.x * 256 + threadIdx.x;
    const int total = B_ * H_ * D_ * D_;
    if (idx >= total) return;
    int bh = idx >> 12;
    int d  = (idx >> 6) & 63;
    float s = 0.f, se = 0.f;
    #pragma unroll
    for (int c = 0; c < NCHUNK; c++) {
        s  += ctxp[(size_t)c * total + idx];
        se += ctxs[(size_t)c * (B_ * H_ * D_) + bh * D_ + d];
    }
    ctx[idx] = s / se;
}

// ---------------------------------------------------------------------------
// out (fused q-softmax): attn[b,n,h*64+e] = softmax_d(q[b,n,h,:]) @ ctx[b,h,:,e]
// Writes fp16. grid (N/128, H, B), 256 threads.
// ---------------------------------------------------------------------------
__global__ __launch_bounds__(256) void out_kernel(
    const float* __restrict__ qkv, const float* __restrict__ ctx,
    __half* __restrict__ attn)
{
    int b = blockIdx.z, h = blockIdx.y, n0 = blockIdx.x * 128;

    __shared__ float Cs[64][64];
    __shared__ float Qs[128][68];

    int tid = threadIdx.x;

    const float* cp = ctx + (size_t)(b * H_ + h) * D_ * D_;
    for (int i = tid * 4; i < 4096; i += 1024)
        *(float4*)&Cs[0][i] = *(const float4*)&cp[i];

    // load q rows + inline softmax over head_dim (thread pair owns one row)
    {
        const float* qbase = qkv + (size_t)(b * N_ + n0) * QKV_N + h * D_;
        int ln = tid >> 1;
        int ld = (tid & 1) * 32;
        float v[32];
        const float* qp = qbase + (size_t)ln * QKV_N + ld;
        #pragma unroll
        for (int j = 0; j < 8; j++) {
            float4 t = *(const float4*)(qp + j * 4);
            v[4*j] = t.x; v[4*j+1] = t.y; v[4*j+2] = t.z; v[4*j+3] = t.w;
        }
        float m = v[0];
        #pragma unroll
        for (int j = 1; j < 32; j++) m = fmaxf(m, v[j]);
        m = fmaxf(m, __shfl_xor_sync(0xffffffffu, m, 1));
        float s = 0.f;
        #pragma unroll
        for (int j = 0; j < 32; j++) { v[j] = __expf(v[j] - m); s += v[j]; }
        s += __shfl_xor_sync(0xffffffffu, s, 1);
        float inv = 1.f / s;
        #pragma unroll
        for (int j = 0; j < 8; j++) {
            float4 o = {v[4*j] * inv, v[4*j+1] * inv, v[4*j+2] * inv, v[4*j+3] * inv};
            *(float4*)&Qs[ln][ld + j * 4] = o;
        }
    }
    __syncthreads();

    int tx = tid & 15, ty = tid >> 4;
    float acc[8][4];
    #pragma unroll
    for (int r = 0; r < 8; r++)
        #pragma unroll
        for (int j = 0; j < 4; j++) acc[r][j] = 0.f;

    #pragma unroll 2
    for (int dc = 0; dc < 16; dc++) {
        float4 cq[8];
        #pragma unroll
        for (int r = 0; r < 8; r++)
            cq[r] = *(float4*)&Qs[ty + 16 * r][dc * 4];
        #pragma unroll
        for (int i = 0; i < 4; i++) {
            float4 c4 = *(float4*)&Cs[dc * 4 + i][tx * 4];
            #pragma unroll
            for (int r = 0; r < 8; r++) {
                float qv = (i == 0) ? cq[r].x : (i == 1) ? cq[r].y : (i == 2) ? cq[r].z : cq[r].w;
                acc[r][0] = fmaf(qv, c4.x, acc[r][0]);
                acc[r][1] = fmaf(qv, c4.y, acc[r][1]);
                acc[r][2] = fmaf(qv, c4.z, acc[r][2]);
                acc[r][3] = fmaf(qv, c4.w, acc[r][3]);
            }
        }
    }

    #pragma unroll
    for (int r = 0; r < 8; r++) {
        int n = n0 + ty + 16 * r;
        __half2 h0 = __floats2half2_rn(acc[r][0], acc[r][1]);
        __half2 h1 = __floats2half2_rn(acc[r][2], acc[r][3]);
        uint2 o = {*(uint32_t*)&h0, *(uint32_t*)&h1};
        *(uint2*)&attn[(size_t)(b * N_ + n) * C_ + h * D_ + tx * 4] = o;
    }
}

// ---------------------------------------------------------------------------
extern "C" void kernel_launch(void* const* d_in, const int* in_sizes, int n_in,
                              void* d_out, int out_size)
{
    (void)in_sizes; (void)n_in; (void)out_size;
    const float* x     = (const float*)d_in[0];
    const float* Wqkv  = (const float*)d_in[1];
    const float* bqkv  = (const float*)d_in[2];
    const float* Wproj = (const float*)d_in[3];
    const float* bproj = (const float*)d_in[4];
    float* out = (float*)d_out;

    float *qkv, *ctx, *ctxp, *ctxs;
    __half *abuf, *wqkvT, *wprojT;
    cudaGetSymbolAddress((void**)&qkv,    g_qkv);
    cudaGetSymbolAddress((void**)&ctx,    g_ctx);
    cudaGetSymbolAddress((void**)&ctxp,   g_ctxp);
    cudaGetSymbolAddress((void**)&ctxs,   g_ctxs);
    cudaGetSymbolAddress((void**)&abuf,   g_abuf);
    cudaGetSymbolAddress((void**)&wqkvT,  g_wqkvT);
    cudaGetSymbolAddress((void**)&wprojT, g_wprojT);

    cudaFuncSetAttribute(gemm_mma_fp16,
                         cudaFuncAttributeMaxDynamicSharedMemorySize, GEMM_SMEM);

    // 0) convert x to fp16 (into abuf); transpose weights to [N,K] fp16
    round_x_kernel<<<M_TOT * C_ / 1024, 256>>>(x, abuf);
    transpose_kernel<<<dim3(QKV_N / 32, C_ / 32), dim3(32, 8)>>>(Wqkv, wqkvT, C_, QKV_N);
    transpose_kernel<<<dim3(C_ / 32, C_ / 32), dim3(32, 8)>>>(Wproj, wprojT, C_, C_);

    // 1) qkv = x @ W_qkv + b_qkv   (fp16 MMA, fp32 accum)
    gemm_mma_fp16<<<dim3(QKV_N / 128, M_TOT / 128), 128, GEMM_SMEM>>>(
        abuf, wqkvT, bqkv, qkv, M_TOT, QKV_N, C_);

    // 2) context = softmax_N(k)^T v, fused:  exp at load + colsum, scale in reduce
    ctx_partial_kernel<<<dim3(B_ * H_, NCHUNK), 256>>>(qkv, ctxp, ctxs);
    ctx_reduce_kernel<<<(B_ * H_ * D_ * D_ + 255) / 256, 256>>>(ctxp, ctxs, ctx);

    // 3) attn = softmax_D(q) @ context (softmax fused in; fp16 out)
    out_kernel<<<dim3(N_ / 128, H_, B_), 256>>>(qkv, ctx, abuf);

    // 4) out = attn @ W_proj + b_proj
    gemm_mma_fp16<<<dim3(C_ / 128, M_TOT / 128), 128, GEMM_SMEM>>>(
        abuf, wprojT, bproj, out, M_TOT, C_, C_);
}